// round 11
// baseline (speedup 1.0000x reference)
#include <cuda_runtime.h>
#include <cuda_fp16.h>
#include <math_constants.h>
#include <cstdint>

#define NN 40000
#define NE 640000
#define ET (NE + NN)   // edges + self loops = 680000
#define NG 64
#define CAP 128        // max in-degree capacity (actual max ~45 for this distribution)

// ---------------- device scratch (no allocations allowed) ----------------
__device__ int   g_cursor[NN];
__device__ int   g_srcs2[(size_t)NN * CAP];
__device__ __align__(16) __half g_h1h[(size_t)NN * 128];
__device__ float g_s1[NN];
__device__ float g_d1[NN];
__device__ __align__(16) float g_h1ln[(size_t)NN * 128];
__device__ __align__(16) __half g_h2h[(size_t)NN * 64];
__device__ float g_s2[NN];
__device__ float g_d2[NN];
__device__ float g_pool[NG * 64];
__device__ int   g_cnt[NG];
__device__ int   g_done;

// ---------------- zero init ----------------
__global__ void zero_kernel() {
    int i = blockIdx.x * blockDim.x + threadIdx.x;
    if (i < NN) g_cursor[i] = 0;
    if (i < NG * 64) g_pool[i] = 0.f;
    if (i < NG) g_cnt[i] = 0;
    if (i == 0) g_done = 0;
}

// ---------------- bucket scatter: one kernel builds adjacency ----------------
__global__ void scatter_kernel(const int* __restrict__ ei) {
    int i = blockIdx.x * blockDim.x + threadIdx.x;
    if (i >= ET) return;
    int src, dst;
    if (i < NE) { src = __ldg(ei + i); dst = __ldg(ei + NE + i); }
    else        { src = dst = i - NE; }
    int pos = atomicAdd(&g_cursor[dst], 1);
    if (pos < CAP) g_srcs2[(size_t)dst * CAP + pos] = src;
}

// ---------------- tf32 tensor-core GEMM + fused scores + fp16 H ----------------
__device__ __forceinline__ uint32_t f2tf(float f) {
    uint32_t r;
    asm("cvt.rna.tf32.f32 %0, %1;" : "=r"(r) : "f"(f));
    return r;
}
__device__ __forceinline__ void mma_tf32(float4& d, const uint32_t a[4], const uint32_t b[2]) {
    asm volatile("mma.sync.aligned.m16n8k8.row.col.f32.tf32.tf32.f32 "
                 "{%0,%1,%2,%3}, {%4,%5,%6,%7}, {%8,%9}, {%0,%1,%2,%3};"
                 : "+f"(d.x), "+f"(d.y), "+f"(d.z), "+f"(d.w)
                 : "r"(a[0]), "r"(a[1]), "r"(a[2]), "r"(a[3]), "r"(b[0]), "r"(b[1]));
}

// H[BM x OUT] = X[BM x 128] @ W[OUT x 128]^T ; S = H a_s ; D = H a_d
template <int OUT>
__global__ __launch_bounds__(256, 2)
void gemm_mma(const float* __restrict__ X, const float* __restrict__ W,
              const float* __restrict__ a_s, const float* __restrict__ a_d,
              __half* __restrict__ H, float* __restrict__ S, float* __restrict__ D) {
    constexpr int IN = 128, BK = 32, BM = 128;
    constexpr int HALF = OUT / 2, NT = HALF / 8, MT = 2;
    constexpr int LDT = BK + 4;
    __shared__ float Xs[BM][LDT];
    __shared__ float Ws[OUT][LDT];
    __shared__ float sS[BM], sD[BM];

    const int tid = threadIdx.x;
    const int lane = tid & 31, warp = tid >> 5;
    const int wm = warp & 3, wn = warp >> 2;
    const int g = lane >> 2, t = lane & 3;
    const int nb = blockIdx.x * BM;

    if (tid < BM) { sS[tid] = 0.f; sD[tid] = 0.f; }

    float4 d[MT][NT];
    #pragma unroll
    for (int mt = 0; mt < MT; mt++)
        #pragma unroll
        for (int nt = 0; nt < NT; nt++) d[mt][nt] = make_float4(0.f, 0.f, 0.f, 0.f);

    for (int kc = 0; kc < IN; kc += BK) {
        #pragma unroll
        for (int p = 0; p < BM / 32; p++) {
            int i = p * 256 + tid;
            int row = i >> 3, q = i & 7;
            int node = nb + row; if (node >= NN) node = NN - 1;
            float4 v = *(const float4*)(X + (size_t)node * IN + kc + q * 4);
            *(float4*)&Xs[row][q * 4] = v;
        }
        #pragma unroll
        for (int p = 0; p < OUT / 32; p++) {
            int i = p * 256 + tid;
            int row = i >> 3, q = i & 7;
            float4 v = *(const float4*)(W + (size_t)row * IN + kc + q * 4);
            *(float4*)&Ws[row][q * 4] = v;
        }
        __syncthreads();
        #pragma unroll
        for (int ks = 0; ks < BK / 8; ks++) {
            int k0 = ks * 8;
            uint32_t a[MT][4];
            #pragma unroll
            for (int mt = 0; mt < MT; mt++) {
                int r = wm * 32 + mt * 16 + g;
                a[mt][0] = f2tf(Xs[r][k0 + t]);
                a[mt][1] = f2tf(Xs[r + 8][k0 + t]);
                a[mt][2] = f2tf(Xs[r][k0 + t + 4]);
                a[mt][3] = f2tf(Xs[r + 8][k0 + t + 4]);
            }
            #pragma unroll
            for (int nt = 0; nt < NT; nt++) {
                int n = wn * HALF + nt * 8 + g;
                uint32_t b[2];
                b[0] = f2tf(Ws[n][k0 + t]);
                b[1] = f2tf(Ws[n][k0 + t + 4]);
                #pragma unroll
                for (int mt = 0; mt < MT; mt++) mma_tf32(d[mt][nt], a[mt], b);
            }
        }
        __syncthreads();
    }

    #pragma unroll
    for (int mt = 0; mt < MT; mt++) {
        int r0 = wm * 32 + mt * 16 + g;
        int node0 = nb + r0, node1 = node0 + 8;
        float sp0 = 0.f, sp1 = 0.f, dp0 = 0.f, dp1 = 0.f;
        #pragma unroll
        for (int nt = 0; nt < NT; nt++) {
            int c0 = wn * HALF + nt * 8 + 2 * t;
            float as0 = __ldg(a_s + c0), as1 = __ldg(a_s + c0 + 1);
            float ad0 = __ldg(a_d + c0), ad1 = __ldg(a_d + c0 + 1);
            float4 v = d[mt][nt];
            sp0 = fmaf(v.x, as0, fmaf(v.y, as1, sp0));
            dp0 = fmaf(v.x, ad0, fmaf(v.y, ad1, dp0));
            sp1 = fmaf(v.z, as0, fmaf(v.w, as1, sp1));
            dp1 = fmaf(v.z, ad0, fmaf(v.w, ad1, dp1));
            if (node0 < NN) *(__half2*)(H + (size_t)node0 * OUT + c0) = __floats2half2_rn(v.x, v.y);
            if (node1 < NN) *(__half2*)(H + (size_t)node1 * OUT + c0) = __floats2half2_rn(v.z, v.w);
        }
        #pragma unroll
        for (int o = 1; o <= 2; o <<= 1) {
            sp0 += __shfl_xor_sync(0xffffffffu, sp0, o);
            sp1 += __shfl_xor_sync(0xffffffffu, sp1, o);
            dp0 += __shfl_xor_sync(0xffffffffu, dp0, o);
            dp1 += __shfl_xor_sync(0xffffffffu, dp1, o);
        }
        if (t == 0) {
            atomicAdd(&sS[r0], sp0);     atomicAdd(&sD[r0], dp0);
            atomicAdd(&sS[r0 + 8], sp1); atomicAdd(&sD[r0 + 8], dp1);
        }
    }
    __syncthreads();
    if (tid < BM) {
        int node = nb + tid;
        if (node < NN) { S[node] = sS[tid]; D[node] = sD[tid]; }
    }
}

// ---------------- vector helpers ----------------
template <int V> struct HVec;
template <> struct HVec<4> {
    static __device__ __forceinline__ void ld(float* f, const __half* p) {
        uint2 t = *(const uint2*)p;
        float2 a = __half22float2(*(__half2*)&t.x);
        float2 b = __half22float2(*(__half2*)&t.y);
        f[0] = a.x; f[1] = a.y; f[2] = b.x; f[3] = b.y;
    }
};
template <> struct HVec<2> {
    static __device__ __forceinline__ void ld(float* f, const __half* p) {
        uint32_t t = *(const uint32_t*)p;
        float2 a = __half22float2(*(__half2*)&t);
        f[0] = a.x; f[1] = a.y;
    }
};
template <int V> struct Vec;
template <> struct Vec<4> {
    static __device__ __forceinline__ void ld(float* f, const float* p) {
        float4 t = *(const float4*)p; f[0] = t.x; f[1] = t.y; f[2] = t.z; f[3] = t.w;
    }
    static __device__ __forceinline__ void st(float* p, const float* f) {
        *(float4*)p = make_float4(f[0], f[1], f[2], f[3]);
    }
};
template <> struct Vec<2> {
    static __device__ __forceinline__ void ld(float* f, const float* p) {
        float2 t = *(const float2*)p; f[0] = t.x; f[1] = t.y;
    }
    static __device__ __forceinline__ void st(float* p, const float* f) {
        *(float2*)p = make_float2(f[0], f[1]);
    }
};

// ---------------- GAT aggregation: warp per dst, online softmax, fp16 gather ----
// POOL variant also runs the final head (mean-pool -> Wl -> Wc) in its last block.
template <int C, bool POOL>
__global__ __launch_bounds__(256)
void gat_agg(const __half* __restrict__ H, const float* __restrict__ S,
             const float* __restrict__ D, const float* __restrict__ bias,
             const float* __restrict__ gamma, const float* __restrict__ beta,
             float* __restrict__ OUT, const int* __restrict__ batch,
             const float* __restrict__ Wl, const float* __restrict__ bl,
             const float* __restrict__ Wc, const float* __restrict__ bc,
             float* __restrict__ final_out) {
    constexpr int V = C / 32;
    int w = (blockIdx.x * blockDim.x + threadIdx.x) >> 5;
    int lane = threadIdx.x & 31;

    if (w < NN) {
        int beg = w * CAP;
        int cnt = min(g_cursor[w], CAP);
        float dsc = __ldg(D + w);
        float m = -CUDART_INF_F, z = 0.f;
        float acc[V];
        #pragma unroll
        for (int v = 0; v < V; v++) acc[v] = 0.f;

        for (int base = 0; base < cnt; base += 32) {
            int j = base + lane;
            int srcj = 0;
            float e = -CUDART_INF_F;
            if (j < cnt) {
                srcj = g_srcs2[beg + j];
                float t = __ldg(S + srcj) + dsc;
                e = (t > 0.f) ? t : 0.2f * t;
            }
            float cm = e;
            #pragma unroll
            for (int o = 16; o; o >>= 1) cm = fmaxf(cm, __shfl_xor_sync(0xffffffffu, cm, o));
            float mnew = fmaxf(m, cm);
            float scale = __expf(m - mnew);
            z *= scale;
            #pragma unroll
            for (int v = 0; v < V; v++) acc[v] *= scale;
            m = mnew;
            float wl = (j < cnt) ? __expf(e - m) : 0.f;
            float zc = wl;
            #pragma unroll
            for (int o = 16; o; o >>= 1) zc += __shfl_xor_sync(0xffffffffu, zc, o);
            z += zc;

            int rem = min(32, cnt - base);
            int k = 0;
            for (; k + 8 <= rem; k += 8) {
                float f[8][V], wg[8];
                #pragma unroll
                for (int u = 0; u < 8; u++) {
                    int sk = __shfl_sync(0xffffffffu, srcj, k + u);
                    wg[u]  = __shfl_sync(0xffffffffu, wl, k + u);
                    HVec<V>::ld(f[u], H + (size_t)sk * C + lane * V);
                }
                #pragma unroll
                for (int u = 0; u < 8; u++)
                    #pragma unroll
                    for (int v = 0; v < V; v++)
                        acc[v] = fmaf(wg[u], f[u][v], acc[v]);
            }
            for (; k < rem; k++) {
                int sk = __shfl_sync(0xffffffffu, srcj, k);
                float wk = __shfl_sync(0xffffffffu, wl, k);
                float f[V];
                HVec<V>::ld(f, H + (size_t)sk * C + lane * V);
                #pragma unroll
                for (int v = 0; v < V; v++) acc[v] = fmaf(wk, f[v], acc[v]);
            }
        }

        float inv = 1.f / z;
        float bi[V], vals[V];
        Vec<V>::ld(bi, bias + lane * V);
        float sum = 0.f;
        #pragma unroll
        for (int v = 0; v < V; v++) {
            float o = fmaf(acc[v], inv, bi[v]);
            o = fmaxf(o, 0.f);
            vals[v] = o;
            sum += o;
        }
        #pragma unroll
        for (int o = 16; o; o >>= 1) sum += __shfl_xor_sync(0xffffffffu, sum, o);
        float mean = sum * (1.f / C);
        float sq = 0.f;
        #pragma unroll
        for (int v = 0; v < V; v++) { float dd = vals[v] - mean; sq = fmaf(dd, dd, sq); }
        #pragma unroll
        for (int o = 16; o; o >>= 1) sq += __shfl_xor_sync(0xffffffffu, sq, o);
        float rstd = rsqrtf(sq * (1.f / C) + 1e-5f);

        float ga[V], be[V], r[V];
        Vec<V>::ld(ga, gamma + lane * V);
        Vec<V>::ld(be, beta + lane * V);
        #pragma unroll
        for (int v = 0; v < V; v++)
            r[v] = fmaf(ga[v] * (vals[v] - mean), rstd, be[v]);

        if (POOL) {
            int b = batch[w];
            #pragma unroll
            for (int v = 0; v < V; v++)
                atomicAdd(&g_pool[b * 64 + lane * V + v], r[v]);
            if (lane == 0) atomicAdd(&g_cnt[b], 1);
        } else {
            Vec<V>::st(OUT + (size_t)w * C + lane * V, r);
        }
    }

    if (POOL) {
        // last finishing block runs the head
        __shared__ bool s_last;
        __shared__ float sp[8][64];
        __syncthreads();
        __threadfence();
        if (threadIdx.x == 0) {
            int old = atomicAdd(&g_done, 1);
            s_last = (old == (int)gridDim.x - 1);
        }
        __syncthreads();
        if (!s_last) return;
        __threadfence();
        int warp = threadIdx.x >> 5;
        // warp handles graphs warp*8 .. warp*8+7
        for (int gi = 0; gi < 8; gi++) {
            int g = warp * 8 + gi;
            float cf = fmaxf((float)g_cnt[g], 1.f);
            sp[warp][lane]      = g_pool[g * 64 + lane] / cf;
            sp[warp][lane + 32] = g_pool[g * 64 + lane + 32] / cf;
            __syncwarp();
            float t = 0.f;
            #pragma unroll 2
            for (int ci = 0; ci < 2; ci++) {
                int c = lane + ci * 32;
                float a = __ldg(bl + c);
                #pragma unroll 8
                for (int k = 0; k < 64; k++)
                    a = fmaf(__ldg(Wl + c * 64 + k), sp[warp][k], a);
                t = fmaf(__ldg(Wc + c), a, t);
            }
            #pragma unroll
            for (int o = 16; o; o >>= 1) t += __shfl_xor_sync(0xffffffffu, t, o);
            if (lane == 0) final_out[g] = t + __ldg(bc);
            __syncwarp();
        }
    }
}

// ---------------- launch ----------------
extern "C" void kernel_launch(void* const* d_in, const int* in_sizes, int n_in,
                              void* d_out, int out_size) {
    const float* x   = (const float*)d_in[0];
    const int*   ei  = (const int*)d_in[1];
    const int*   bat = (const int*)d_in[2];
    const float* W1  = (const float*)d_in[3];
    const float* a1s = (const float*)d_in[4];
    const float* a1d = (const float*)d_in[5];
    const float* b1  = (const float*)d_in[6];
    const float* g1  = (const float*)d_in[7];
    const float* be1 = (const float*)d_in[8];
    const float* W2  = (const float*)d_in[9];
    const float* a2s = (const float*)d_in[10];
    const float* a2d = (const float*)d_in[11];
    const float* b2  = (const float*)d_in[12];
    const float* g2  = (const float*)d_in[13];
    const float* be2 = (const float*)d_in[14];
    const float* Wl  = (const float*)d_in[15];
    const float* bl  = (const float*)d_in[16];
    const float* Wc  = (const float*)d_in[17];
    const float* bc  = (const float*)d_in[18];
    float* out = (float*)d_out;

    void *p_h1, *p_s1, *p_d1, *p_h1ln, *p_h2, *p_s2, *p_d2;
    cudaGetSymbolAddress(&p_h1, g_h1h);
    cudaGetSymbolAddress(&p_s1, g_s1);
    cudaGetSymbolAddress(&p_d1, g_d1);
    cudaGetSymbolAddress(&p_h1ln, g_h1ln);
    cudaGetSymbolAddress(&p_h2, g_h2h);
    cudaGetSymbolAddress(&p_s2, g_s2);
    cudaGetSymbolAddress(&p_d2, g_d2);

    zero_kernel<<<(NN + 255) / 256, 256>>>();
    scatter_kernel<<<(ET + 255) / 256, 256>>>(ei);

    // layer 1
    gemm_mma<128><<<(NN + 127) / 128, 256>>>(
        x, W1, a1s, a1d, (__half*)p_h1, (float*)p_s1, (float*)p_d1);
    gat_agg<128, false><<<(NN + 7) / 8, 256>>>(
        (const __half*)p_h1, (const float*)p_s1, (const float*)p_d1,
        b1, g1, be1, (float*)p_h1ln, nullptr,
        nullptr, nullptr, nullptr, nullptr, nullptr);
    // layer 2 (pooling + head fused into aggregation)
    gemm_mma<64><<<(NN + 127) / 128, 256>>>(
        (const float*)p_h1ln, W2, a2s, a2d, (__half*)p_h2, (float*)p_s2, (float*)p_d2);
    gat_agg<64, true><<<(NN + 7) / 8, 256>>>(
        (const __half*)p_h2, (const float*)p_s2, (const float*)p_d2,
        b2, g2, be2, nullptr, bat,
        Wl, bl, Wc, bc, out);
}

// round 13
// speedup vs baseline: 2.0715x; 2.0715x over previous
#include <cuda_runtime.h>
#include <cuda_fp16.h>
#include <math_constants.h>
#include <cstdint>

#define NN 40000
#define NE 640000
#define ET (NE + NN)   // edges + self loops = 680000
#define NG 64
#define SCAN_B 512
#define SCAN_NB ((NN + SCAN_B - 1) / SCAN_B)   // 79

// ---------------- device scratch (no allocations allowed) ----------------
__device__ int   g_count[NN];
__device__ int   g_off[NN + 1];   // block-local inclusive scan; fixed up via csr_off()
__device__ int   g_cursor[NN];
__device__ int   g_bsum[SCAN_NB]; // exclusive scan of block sums
__device__ int   g_srcs[ET];
__device__ __align__(16) __half g_h1h[(size_t)NN * 128];
__device__ float g_s1[NN];
__device__ float g_d1[NN];
__device__ __align__(16) __half g_h1lnh[(size_t)NN * 128];   // fp16 LN output (feeds tf32 MMA)
__device__ __align__(16) __half g_h2h[(size_t)NN * 64];
__device__ float g_s2[NN];
__device__ float g_d2[NN];
__device__ float g_pool[NG * 64];
__device__ int   g_cnt[NG];

// global CSR offset: g_off holds block-local inclusive sums, g_bsum the block bases
__device__ __forceinline__ int csr_off(int i) {
    return (i == 0) ? 0 : g_off[i] + g_bsum[(i - 1) >> 9];   // 512 = SCAN_B
}

// ---------------- zero init ----------------
__global__ void zero_kernel() {
    int i = blockIdx.x * blockDim.x + threadIdx.x;
    if (i < NN) { g_count[i] = 0; g_cursor[i] = 0; }
    if (i < NG * 64) g_pool[i] = 0.f;
    if (i < NG) g_cnt[i] = 0;
}

// ---------------- CSR build: histogram ----------------
__global__ void hist_kernel(const int* __restrict__ ei) {
    int i = blockIdx.x * blockDim.x + threadIdx.x;
    if (i >= ET) return;
    int dst = (i < NE) ? ei[NE + i] : (i - NE);
    atomicAdd(&g_count[dst], 1);
}

// ---------------- CSR build: block-local scan + block sums ----------------
__global__ void scan_block() {
    __shared__ int ws[SCAN_B / 32];
    int b = blockIdx.x, t = threadIdx.x;
    int lane = t & 31, wid = t >> 5;
    int i = b * SCAN_B + t;
    int v = (i < NN) ? g_count[i] : 0;
    int x = v;
    #pragma unroll
    for (int o = 1; o < 32; o <<= 1) {
        int y = __shfl_up_sync(0xffffffffu, x, o);
        if (lane >= o) x += y;
    }
    if (lane == 31) ws[wid] = x;
    __syncthreads();
    if (wid == 0) {
        int s = (lane < SCAN_B / 32) ? ws[lane] : 0;
        #pragma unroll
        for (int o = 1; o < 32; o <<= 1) {
            int y = __shfl_up_sync(0xffffffffu, s, o);
            if (lane >= o) s += y;
        }
        if (lane < SCAN_B / 32) ws[lane] = s;
    }
    __syncthreads();
    int incl = (wid ? ws[wid - 1] : 0) + x;
    if (i < NN) g_off[i + 1] = incl;
    if (t == SCAN_B - 1) g_bsum[b] = incl;
}

__global__ void scan_tops() {   // exclusive scan of 79 block sums
    __shared__ int ws[4];
    int t = threadIdx.x, lane = t & 31, wid = t >> 5;
    int v = (t < SCAN_NB) ? g_bsum[t] : 0;
    int x = v;
    #pragma unroll
    for (int o = 1; o < 32; o <<= 1) {
        int y = __shfl_up_sync(0xffffffffu, x, o);
        if (lane >= o) x += y;
    }
    if (lane == 31) ws[wid] = x;
    __syncthreads();
    if (wid == 0) {
        int s = (lane < 4) ? ws[lane] : 0;
        #pragma unroll
        for (int o = 1; o < 4; o <<= 1) {
            int y = __shfl_up_sync(0xffffffffu, s, o);
            if (lane >= o) s += y;
        }
        if (lane < 4) ws[lane] = s;
    }
    __syncthreads();
    int incl = (wid ? ws[wid - 1] : 0) + x;
    if (t < SCAN_NB) g_bsum[t] = incl - v;
}

// ---------------- CSR build: scatter src ids into dst buckets ----------------
__global__ void scatter_kernel(const int* __restrict__ ei) {
    int i = blockIdx.x * blockDim.x + threadIdx.x;
    if (i >= ET) return;
    int src, dst;
    if (i < NE) { src = ei[i]; dst = ei[NE + i]; }
    else        { src = dst = i - NE; }
    int base = csr_off(dst);
    int pos = atomicAdd(&g_cursor[dst], 1);
    g_srcs[base + pos] = src;
}

// ---------------- tf32 tensor-core GEMM + fused scores + fp16 H ----------------
__device__ __forceinline__ uint32_t f2tf(float f) {
    uint32_t r;
    asm("cvt.rna.tf32.f32 %0, %1;" : "=r"(r) : "f"(f));
    return r;
}
__device__ __forceinline__ void mma_tf32(float4& d, const uint32_t a[4], const uint32_t b[2]) {
    asm volatile("mma.sync.aligned.m16n8k8.row.col.f32.tf32.tf32.f32 "
                 "{%0,%1,%2,%3}, {%4,%5,%6,%7}, {%8,%9}, {%0,%1,%2,%3};"
                 : "+f"(d.x), "+f"(d.y), "+f"(d.z), "+f"(d.w)
                 : "r"(a[0]), "r"(a[1]), "r"(a[2]), "r"(a[3]), "r"(b[0]), "r"(b[1]));
}

// H[BM x OUT] = X[BM x 128] @ W[OUT x 128]^T ; S = H a_s ; D = H a_d
// XT = float or __half (fp16 input converts in the smem stage; feeds tf32 anyway)
template <int OUT, typename XT>
__global__ __launch_bounds__(256, 2)
void gemm_mma(const XT* __restrict__ X, const float* __restrict__ W,
              const float* __restrict__ a_s, const float* __restrict__ a_d,
              __half* __restrict__ H, float* __restrict__ S, float* __restrict__ D) {
    constexpr int IN = 128, BK = 32, BM = 128;
    constexpr int HALF = OUT / 2, NT = HALF / 8, MT = 2;
    constexpr int LDT = BK + 4;
    constexpr bool ISH = (sizeof(XT) == 2);
    __shared__ float Xs[BM][LDT];
    __shared__ float Ws[OUT][LDT];
    __shared__ float sS[BM], sD[BM];

    const int tid = threadIdx.x;
    const int lane = tid & 31, warp = tid >> 5;
    const int wm = warp & 3, wn = warp >> 2;
    const int g = lane >> 2, t = lane & 3;
    const int nb = blockIdx.x * BM;

    if (tid < BM) { sS[tid] = 0.f; sD[tid] = 0.f; }

    float4 d[MT][NT];
    #pragma unroll
    for (int mt = 0; mt < MT; mt++)
        #pragma unroll
        for (int nt = 0; nt < NT; nt++) d[mt][nt] = make_float4(0.f, 0.f, 0.f, 0.f);

    for (int kc = 0; kc < IN; kc += BK) {
        #pragma unroll
        for (int p = 0; p < BM / 32; p++) {
            int i = p * 256 + tid;
            int row = i >> 3, q = i & 7;
            int node = nb + row; if (node >= NN) node = NN - 1;
            float4 v;
            if (ISH) {
                uint2 u = *(const uint2*)((const __half*)X + (size_t)node * IN + kc + q * 4);
                float2 a = __half22float2(*(__half2*)&u.x);
                float2 b = __half22float2(*(__half2*)&u.y);
                v = make_float4(a.x, a.y, b.x, b.y);
            } else {
                v = *(const float4*)((const float*)X + (size_t)node * IN + kc + q * 4);
            }
            *(float4*)&Xs[row][q * 4] = v;
        }
        #pragma unroll
        for (int p = 0; p < OUT / 32; p++) {
            int i = p * 256 + tid;
            int row = i >> 3, q = i & 7;
            float4 v = *(const float4*)(W + (size_t)row * IN + kc + q * 4);
            *(float4*)&Ws[row][q * 4] = v;
        }
        __syncthreads();
        #pragma unroll
        for (int ks = 0; ks < BK / 8; ks++) {
            int k0 = ks * 8;
            uint32_t a[MT][4];
            #pragma unroll
            for (int mt = 0; mt < MT; mt++) {
                int r = wm * 32 + mt * 16 + g;
                a[mt][0] = f2tf(Xs[r][k0 + t]);
                a[mt][1] = f2tf(Xs[r + 8][k0 + t]);
                a[mt][2] = f2tf(Xs[r][k0 + t + 4]);
                a[mt][3] = f2tf(Xs[r + 8][k0 + t + 4]);
            }
            #pragma unroll
            for (int nt = 0; nt < NT; nt++) {
                int n = wn * HALF + nt * 8 + g;
                uint32_t b[2];
                b[0] = f2tf(Ws[n][k0 + t]);
                b[1] = f2tf(Ws[n][k0 + t + 4]);
                #pragma unroll
                for (int mt = 0; mt < MT; mt++) mma_tf32(d[mt][nt], a[mt], b);
            }
        }
        __syncthreads();
    }

    #pragma unroll
    for (int mt = 0; mt < MT; mt++) {
        int r0 = wm * 32 + mt * 16 + g;
        int node0 = nb + r0, node1 = node0 + 8;
        float sp0 = 0.f, sp1 = 0.f, dp0 = 0.f, dp1 = 0.f;
        #pragma unroll
        for (int nt = 0; nt < NT; nt++) {
            int c0 = wn * HALF + nt * 8 + 2 * t;
            float as0 = __ldg(a_s + c0), as1 = __ldg(a_s + c0 + 1);
            float ad0 = __ldg(a_d + c0), ad1 = __ldg(a_d + c0 + 1);
            float4 v = d[mt][nt];
            sp0 = fmaf(v.x, as0, fmaf(v.y, as1, sp0));
            dp0 = fmaf(v.x, ad0, fmaf(v.y, ad1, dp0));
            sp1 = fmaf(v.z, as0, fmaf(v.w, as1, sp1));
            dp1 = fmaf(v.z, ad0, fmaf(v.w, ad1, dp1));
            if (node0 < NN) *(__half2*)(H + (size_t)node0 * OUT + c0) = __floats2half2_rn(v.x, v.y);
            if (node1 < NN) *(__half2*)(H + (size_t)node1 * OUT + c0) = __floats2half2_rn(v.z, v.w);
        }
        #pragma unroll
        for (int o = 1; o <= 2; o <<= 1) {
            sp0 += __shfl_xor_sync(0xffffffffu, sp0, o);
            sp1 += __shfl_xor_sync(0xffffffffu, sp1, o);
            dp0 += __shfl_xor_sync(0xffffffffu, dp0, o);
            dp1 += __shfl_xor_sync(0xffffffffu, dp1, o);
        }
        if (t == 0) {
            atomicAdd(&sS[r0], sp0);     atomicAdd(&sD[r0], dp0);
            atomicAdd(&sS[r0 + 8], sp1); atomicAdd(&sD[r0 + 8], dp1);
        }
    }
    __syncthreads();
    if (tid < BM) {
        int node = nb + tid;
        if (node < NN) { S[node] = sS[tid]; D[node] = sD[tid]; }
    }
}

// ---------------- vector helpers ----------------
template <int V> struct HVec;
template <> struct HVec<4> {
    static __device__ __forceinline__ void ld(float* f, const __half* p) {
        uint2 t = *(const uint2*)p;
        float2 a = __half22float2(*(__half2*)&t.x);
        float2 b = __half22float2(*(__half2*)&t.y);
        f[0] = a.x; f[1] = a.y; f[2] = b.x; f[3] = b.y;
    }
    static __device__ __forceinline__ void st(__half* p, const float* f) {
        uint2 t;
        __half2 h0 = __floats2half2_rn(f[0], f[1]);
        __half2 h1 = __floats2half2_rn(f[2], f[3]);
        t.x = *(uint32_t*)&h0; t.y = *(uint32_t*)&h1;
        *(uint2*)p = t;
    }
};
template <> struct HVec<2> {
    static __device__ __forceinline__ void ld(float* f, const __half* p) {
        uint32_t t = *(const uint32_t*)p;
        float2 a = __half22float2(*(__half2*)&t);
        f[0] = a.x; f[1] = a.y;
    }
    static __device__ __forceinline__ void st(__half* p, const float* f) {
        __half2 h = __floats2half2_rn(f[0], f[1]);
        *(uint32_t*)p = *(uint32_t*)&h;
    }
};
template <int V> struct Vec;
template <> struct Vec<4> {
    static __device__ __forceinline__ void ld(float* f, const float* p) {
        float4 t = *(const float4*)p; f[0] = t.x; f[1] = t.y; f[2] = t.z; f[3] = t.w;
    }
};
template <> struct Vec<2> {
    static __device__ __forceinline__ void ld(float* f, const float* p) {
        float2 t = *(const float2*)p; f[0] = t.x; f[1] = t.y;
    }
};

// ---------------- GAT aggregation: warp per dst, online softmax, fp16 gather ----
// HOUT: write LN output as fp16 (feeds next tf32 GEMM; no extra precision loss)
template <int C, bool POOL, bool HOUT>
__global__ __launch_bounds__(256)
void gat_agg(const __half* __restrict__ H, const float* __restrict__ S,
             const float* __restrict__ D, const float* __restrict__ bias,
             const float* __restrict__ gamma, const float* __restrict__ beta,
             void* __restrict__ OUT, const int* __restrict__ batch) {
    constexpr int V = C / 32;
    int w = (blockIdx.x * blockDim.x + threadIdx.x) >> 5;
    if (w >= NN) return;
    int lane = threadIdx.x & 31;
    int beg = csr_off(w), end = csr_off(w + 1);
    float dsc = __ldg(D + w);
    float m = -CUDART_INF_F, z = 0.f;
    float acc[V];
    #pragma unroll
    for (int v = 0; v < V; v++) acc[v] = 0.f;

    for (int base = beg; base < end; base += 32) {
        int j = base + lane;
        int srcj = 0;
        float e = -CUDART_INF_F;
        if (j < end) {
            srcj = g_srcs[j];
            float t = __ldg(S + srcj) + dsc;
            e = (t > 0.f) ? t : 0.2f * t;
        }
        float cm = e;
        #pragma unroll
        for (int o = 16; o; o >>= 1) cm = fmaxf(cm, __shfl_xor_sync(0xffffffffu, cm, o));
        float mnew = fmaxf(m, cm);
        float scale = __expf(m - mnew);
        z *= scale;
        #pragma unroll
        for (int v = 0; v < V; v++) acc[v] *= scale;
        m = mnew;
        float wl = (j < end) ? __expf(e - m) : 0.f;
        float zc = wl;
        #pragma unroll
        for (int o = 16; o; o >>= 1) zc += __shfl_xor_sync(0xffffffffu, zc, o);
        z += zc;

        int cnt = min(32, end - base);
        int k = 0;
        for (; k + 8 <= cnt; k += 8) {
            float f[8][V], wg[8];
            #pragma unroll
            for (int u = 0; u < 8; u++) {
                int sk = __shfl_sync(0xffffffffu, srcj, k + u);
                wg[u]  = __shfl_sync(0xffffffffu, wl, k + u);
                HVec<V>::ld(f[u], H + (size_t)sk * C + lane * V);
            }
            #pragma unroll
            for (int u = 0; u < 8; u++)
                #pragma unroll
                for (int v = 0; v < V; v++)
                    acc[v] = fmaf(wg[u], f[u][v], acc[v]);
        }
        for (; k < cnt; k++) {
            int sk = __shfl_sync(0xffffffffu, srcj, k);
            float wk = __shfl_sync(0xffffffffu, wl, k);
            float f[V];
            HVec<V>::ld(f, H + (size_t)sk * C + lane * V);
            #pragma unroll
            for (int v = 0; v < V; v++) acc[v] = fmaf(wk, f[v], acc[v]);
        }
    }

    float inv = 1.f / z;
    float bi[V], vals[V];
    Vec<V>::ld(bi, bias + lane * V);
    float sum = 0.f;
    #pragma unroll
    for (int v = 0; v < V; v++) {
        float o = fmaf(acc[v], inv, bi[v]);
        o = fmaxf(o, 0.f);
        vals[v] = o;
        sum += o;
    }
    #pragma unroll
    for (int o = 16; o; o >>= 1) sum += __shfl_xor_sync(0xffffffffu, sum, o);
    float mean = sum * (1.f / C);
    float sq = 0.f;
    #pragma unroll
    for (int v = 0; v < V; v++) { float dd = vals[v] - mean; sq = fmaf(dd, dd, sq); }
    #pragma unroll
    for (int o = 16; o; o >>= 1) sq += __shfl_xor_sync(0xffffffffu, sq, o);
    float rstd = rsqrtf(sq * (1.f / C) + 1e-5f);

    float ga[V], be[V], r[V];
    Vec<V>::ld(ga, gamma + lane * V);
    Vec<V>::ld(be, beta + lane * V);
    #pragma unroll
    for (int v = 0; v < V; v++)
        r[v] = fmaf(ga[v] * (vals[v] - mean), rstd, be[v]);

    if (POOL) {
        int b = batch[w];
        #pragma unroll
        for (int v = 0; v < V; v++)
            atomicAdd(&g_pool[b * 64 + lane * V + v], r[v]);
        if (lane == 0) atomicAdd(&g_cnt[b], 1);
    } else if (HOUT) {
        HVec<V>::st((__half*)OUT + (size_t)w * C + lane * V, r);
    } else {
        float* fo = (float*)OUT + (size_t)w * C + lane * V;
        #pragma unroll
        for (int v = 0; v < V; v++) fo[v] = r[v];
    }
}

// ---------------- head: mean pool -> Wl -> Wc ----------------
__global__ void head_kernel(const float* __restrict__ Wl, const float* __restrict__ bl,
                            const float* __restrict__ Wc, const float* __restrict__ bc,
                            float* __restrict__ out) {
    int g = blockIdx.x;
    int c = threadIdx.x;   // 64
    __shared__ float pooled[64];
    __shared__ float red[64];
    float cf = fmaxf((float)g_cnt[g], 1.f);
    pooled[c] = g_pool[g * 64 + c] / cf;
    __syncthreads();
    float a = bl[c];
    #pragma unroll 8
    for (int k = 0; k < 64; k++) a = fmaf(Wl[c * 64 + k], pooled[k], a);
    red[c] = a * Wc[c];
    __syncthreads();
    #pragma unroll
    for (int st = 32; st; st >>= 1) {
        if (c < st) red[c] += red[c + st];
        __syncthreads();
    }
    if (c == 0) out[g] = red[0] + bc[0];
}

// ---------------- launch ----------------
extern "C" void kernel_launch(void* const* d_in, const int* in_sizes, int n_in,
                              void* d_out, int out_size) {
    const float* x   = (const float*)d_in[0];
    const int*   ei  = (const int*)d_in[1];
    const int*   bat = (const int*)d_in[2];
    const float* W1  = (const float*)d_in[3];
    const float* a1s = (const float*)d_in[4];
    const float* a1d = (const float*)d_in[5];
    const float* b1  = (const float*)d_in[6];
    const float* g1  = (const float*)d_in[7];
    const float* be1 = (const float*)d_in[8];
    const float* W2  = (const float*)d_in[9];
    const float* a2s = (const float*)d_in[10];
    const float* a2d = (const float*)d_in[11];
    const float* b2  = (const float*)d_in[12];
    const float* g2  = (const float*)d_in[13];
    const float* be2 = (const float*)d_in[14];
    const float* Wl  = (const float*)d_in[15];
    const float* bl  = (const float*)d_in[16];
    const float* Wc  = (const float*)d_in[17];
    const float* bc  = (const float*)d_in[18];
    float* out = (float*)d_out;

    void *p_h1, *p_s1, *p_d1, *p_h1ln, *p_h2, *p_s2, *p_d2;
    cudaGetSymbolAddress(&p_h1, g_h1h);
    cudaGetSymbolAddress(&p_s1, g_s1);
    cudaGetSymbolAddress(&p_d1, g_d1);
    cudaGetSymbolAddress(&p_h1ln, g_h1lnh);
    cudaGetSymbolAddress(&p_h2, g_h2h);
    cudaGetSymbolAddress(&p_s2, g_s2);
    cudaGetSymbolAddress(&p_d2, g_d2);

    zero_kernel<<<(NN + 255) / 256, 256>>>();
    hist_kernel<<<(ET + 255) / 256, 256>>>(ei);
    scan_block<<<SCAN_NB, SCAN_B>>>();
    scan_tops<<<1, 128>>>();
    scatter_kernel<<<(ET + 255) / 256, 256>>>(ei);

    // layer 1
    gemm_mma<128, float><<<(NN + 127) / 128, 256>>>(
        x, W1, a1s, a1d, (__half*)p_h1, (float*)p_s1, (float*)p_d1);
    gat_agg<128, false, true><<<(NN + 7) / 8, 256>>>(
        (const __half*)p_h1, (const float*)p_s1, (const float*)p_d1,
        b1, g1, be1, p_h1ln, nullptr);
    // layer 2 (pooling fused into aggregation); X input is fp16 LN output
    gemm_mma<64, __half><<<(NN + 127) / 128, 256>>>(
        (const __half*)p_h1ln, W2, a2s, a2d, (__half*)p_h2, (float*)p_s2, (float*)p_d2);
    gat_agg<64, true, false><<<(NN + 7) / 8, 256>>>(
        (const __half*)p_h2, (const float*)p_s2, (const float*)p_d2,
        b2, g2, be2, nullptr, bat);
    // head
    head_kernel<<<NG, 64>>>(Wl, bl, Wc, bc, out);
}